// round 5
// baseline (speedup 1.0000x reference)
#include <cuda_runtime.h>

#define BATCH 4
#define NPTS 8192
#define PAD 32
#define STRIDE (NPTS + 2 * PAD)
#define BINS 8192
#define SORT_THREADS 1024
#define W 2048
#define NN_THREADS 256
#define QPB 128                              // queries per block
#define NN_BLOCKS_X (NPTS / QPB)             // 64
#define NN_BLOCKS (NN_BLOCKS_X * 8)          // 512
#define FULLMASK 0xffffffffu
#define DELTA 0.005f   // >= x-bucket width (12/8192); certificate margin

// Sorted (by quantized x) point quads per (set,batch): (x,y,z,|p|^2) + sentinels.
__device__ float4 g_pts[8][STRIDE];
__device__ float g_bsum[NN_BLOCKS];
__device__ unsigned g_count;   // zero-init; reset by last block each run

__device__ __forceinline__ int bucket(float x) {
    int b = (int)((x + 6.0f) * (BINS / 12.0f));
    return min(max(b, 0), BINS - 1);
}
__device__ __forceinline__ float dquad(float m2x, float m2y, float m2z, float4 t) {
    return fmaf(m2x, t.x, fmaf(m2y, t.y, fmaf(m2z, t.z, t.w)));
}

// ---------------------------------------------------------------------------
// Counting sort by 13-bit quantized x. One block per (set,batch).
// ---------------------------------------------------------------------------
__global__ __launch_bounds__(SORT_THREADS)
void sort_kernel(const float* __restrict__ p1, const float* __restrict__ p2) {
    __shared__ unsigned hist[BINS];        // 32 KB
    __shared__ unsigned wtot[32];
    const int tid = threadIdx.x, lane = tid & 31, wid = tid >> 5;
    const int set = blockIdx.x >> 2;
    const int b = blockIdx.x & 3;
    const float* __restrict__ P = (set ? p2 : p1) + (size_t)b * NPTS * 3;

    for (int i = tid; i < BINS; i += SORT_THREADS) hist[i] = 0;
    __syncthreads();

    // Load coords once into registers; histogram.
    float xv[8], yv[8], zv[8];
#pragma unroll
    for (int k = 0; k < 8; k++) {
        int i = tid + k * SORT_THREADS;
        xv[k] = P[3 * i]; yv[k] = P[3 * i + 1]; zv[k] = P[3 * i + 2];
        atomicAdd(&hist[bucket(xv[k])], 1u);
    }
    __syncthreads();

    // Exclusive scan of hist[8192]: 8 bins/thread + hierarchical warp scan.
    const int base = tid * 8;
    unsigned loc[8], s = 0;
#pragma unroll
    for (int j = 0; j < 8; j++) { loc[j] = s; s += hist[base + j]; }
    unsigned v = s;
#pragma unroll
    for (int o = 1; o < 32; o <<= 1) {
        unsigned n = __shfl_up_sync(FULLMASK, v, o);
        if (lane >= o) v += n;
    }
    if (lane == 31) wtot[wid] = v;
    __syncthreads();
    if (tid < 32) {
        unsigned w = wtot[tid];
#pragma unroll
        for (int o = 1; o < 32; o <<= 1) {
            unsigned n = __shfl_up_sync(FULLMASK, w, o);
            if (tid >= o) w += n;
        }
        wtot[tid] = w;
    }
    __syncthreads();
    unsigned thr_excl = v - s + (wid ? wtot[wid - 1] : 0u);
    __syncthreads();
#pragma unroll
    for (int j = 0; j < 8; j++) hist[base + j] = thr_excl + loc[j];
    __syncthreads();

    // Scatter quads from registers to sorted positions.
    float4* dst = g_pts[blockIdx.x];
#pragma unroll
    for (int k = 0; k < 8; k++) {
        unsigned pos = atomicAdd(&hist[bucket(xv[k])], 1u);
        dst[PAD + pos] = make_float4(xv[k], yv[k], zv[k],
            xv[k] * xv[k] + yv[k] * yv[k] + zv[k] * zv[k]);
    }
    for (int i = tid; i < PAD; i += SORT_THREADS) {
        dst[i]              = make_float4(-1e30f, 0.f, 0.f, 3.0e38f);
        dst[PAD + NPTS + i] = make_float4( 1e30f, 0.f, 0.f, 3.0e38f);
    }
}

// ---------------------------------------------------------------------------
// NN: smem window; per query-group, one warp scans right, one scans left.
// Sides share best-so-far via smem (stale reads are conservative -> exact).
// ---------------------------------------------------------------------------
__global__ __launch_bounds__(NN_THREADS)
void nn_kernel(float* __restrict__ out) {
    __shared__ __align__(16) float4 s_win[W];   // 32 KB
    __shared__ float sR[QPB], sL[QPB];
    __shared__ float sred[8];
    __shared__ bool s_last;

    const int tid = threadIdx.x, lane = tid & 31, wid = tid >> 5;
    const int g = wid & 3, side = wid >> 2;     // 0: right, 1: left
    const int db  = blockIdx.y;
    const int dir = db >> 2, b = db & 3;
    const float4* __restrict__ Q = g_pts[(dir ? 4 : 0) + b];
    const float4* __restrict__ T = g_pts[(dir ? 0 : 4) + b];

    const int qslot = g * 32 + lane;            // query slot within block
    const float4 q = Q[PAD + blockIdx.x * QPB + qslot];
    const float qx = q.x, qsq = q.w;
    const float m2x = -2.f * q.x, m2y = -2.f * q.y, m2z = -2.f * q.z;

    // Block-uniform window placement (binary search on block-mid query x).
    const float xmid = Q[PAD + blockIdx.x * QPB + QPB / 2].x;
    int lo = 0, hi = NPTS;
#pragma unroll
    for (int s = 0; s < 13; s++) {
        int mid = (lo + hi) >> 1;
        if (T[PAD + mid].x < xmid) lo = mid + 1; else hi = mid;
    }
    int wstart = min(max(lo - W / 2, 0), NPTS - W);

    for (int i = tid; i < W; i += NN_THREADS)
        s_win[i] = T[PAD + wstart + i];
    if (tid < QPB) { sR[tid] = 3.0e38f; sL[tid] = 3.0e38f; }
    __syncthreads();

    // Per-group center in window (group lane-16 query x; uniform across both warps).
    const float xw = __shfl_sync(FULLMASK, qx, 16);
    int l2 = 0, h2 = W;
#pragma unroll
    for (int s = 0; s < 11; s++) {
        int mid = (l2 + h2) >> 1;
        if (s_win[mid].x < xw) l2 = mid + 1; else h2 = mid;
    }

    float* mine  = side ? sL : sR;
    volatile float* other = side ? (volatile float*)sR : (volatile float*)sL;
    float b0 = 3.0e38f, b1 = 3.0e38f, b2 = 3.0e38f, b3 = 3.0e38f;
    int p = l2;
    bool done = false, glob = false;

    if (side == 0) {                            // ---- right scan ----
        while (!done) {
            if (p + 32 > W) { glob = true; break; }
#pragma unroll
            for (int j = 0; j < 32; j += 4) {
                float4 t0 = s_win[p + j], t1 = s_win[p + j + 1];
                float4 t2 = s_win[p + j + 2], t3 = s_win[p + j + 3];
                b0 = fminf(b0, dquad(m2x, m2y, m2z, t0));
                b1 = fminf(b1, dquad(m2x, m2y, m2z, t1));
                b2 = fminf(b2, dquad(m2x, m2y, m2z, t2));
                b3 = fminf(b3, dquad(m2x, m2y, m2z, t3));
            }
            float lx = s_win[p + 31].x;
            p += 32;
            float bm = fminf(fminf(b0, b1), fminf(b2, b3));
            mine[qslot] = bm;
            float cmb = fminf(bm, other[qslot]);
            float tt = lx - qx - DELTA;
            done = __all_sync(FULLMASK, (tt > 0.f) && (tt * tt >= cmb + qsq));
        }
        int gp = wstart + p;
        while (glob) {
#pragma unroll
            for (int j = 0; j < 32; j += 4) {
                float4 t0 = T[PAD + gp + j],     t1 = T[PAD + gp + j + 1];
                float4 t2 = T[PAD + gp + j + 2], t3 = T[PAD + gp + j + 3];
                b0 = fminf(b0, dquad(m2x, m2y, m2z, t0));
                b1 = fminf(b1, dquad(m2x, m2y, m2z, t1));
                b2 = fminf(b2, dquad(m2x, m2y, m2z, t2));
                b3 = fminf(b3, dquad(m2x, m2y, m2z, t3));
            }
            float lx = T[PAD + gp + 31].x;
            gp += 32;
            float bm = fminf(fminf(b0, b1), fminf(b2, b3));
            mine[qslot] = bm;
            float cmb = fminf(bm, other[qslot]);
            float tt = lx - qx - DELTA;
            glob = !__all_sync(FULLMASK, (tt > 0.f) && (tt * tt >= cmb + qsq));
        }
    } else {                                    // ---- left scan ----
        while (!done) {
            if (p < 32) { glob = true; break; }
            p -= 32;
#pragma unroll
            for (int j = 0; j < 32; j += 4) {
                float4 t0 = s_win[p + j], t1 = s_win[p + j + 1];
                float4 t2 = s_win[p + j + 2], t3 = s_win[p + j + 3];
                b0 = fminf(b0, dquad(m2x, m2y, m2z, t0));
                b1 = fminf(b1, dquad(m2x, m2y, m2z, t1));
                b2 = fminf(b2, dquad(m2x, m2y, m2z, t2));
                b3 = fminf(b3, dquad(m2x, m2y, m2z, t3));
            }
            float fx = s_win[p].x;
            float bm = fminf(fminf(b0, b1), fminf(b2, b3));
            mine[qslot] = bm;
            float cmb = fminf(bm, other[qslot]);
            float tt = qx - fx - DELTA;
            done = __all_sync(FULLMASK, (tt > 0.f) && (tt * tt >= cmb + qsq));
        }
        int gp = wstart + p;
        while (glob) {
            gp -= 32;
#pragma unroll
            for (int j = 0; j < 32; j += 4) {
                float4 t0 = T[PAD + gp + j],     t1 = T[PAD + gp + j + 1];
                float4 t2 = T[PAD + gp + j + 2], t3 = T[PAD + gp + j + 3];
                b0 = fminf(b0, dquad(m2x, m2y, m2z, t0));
                b1 = fminf(b1, dquad(m2x, m2y, m2z, t1));
                b2 = fminf(b2, dquad(m2x, m2y, m2z, t2));
                b3 = fminf(b3, dquad(m2x, m2y, m2z, t3));
            }
            float fx = T[PAD + gp].x;
            float bm = fminf(fminf(b0, b1), fminf(b2, b3));
            mine[qslot] = bm;
            float cmb = fminf(bm, other[qslot]);
            float tt = qx - fx - DELTA;
            glob = !__all_sync(FULLMASK, (tt > 0.f) && (tt * tt >= cmb + qsq));
        }
    }
    __syncthreads();

    // Exact per-query min = min(right, left) + |q|^2 (side-0 warps only).
    float d2 = 0.f;
    if (side == 0) d2 = fminf(sR[qslot], sL[qslot]) + qsq;

#pragma unroll
    for (int o = 16; o; o >>= 1) d2 += __shfl_down_sync(FULLMASK, d2, o);
    if (lane == 0) sred[wid] = d2;
    __syncthreads();
    if (tid == 0) {
        float w = 0.f;
#pragma unroll
        for (int i = 0; i < 8; i++) w += sred[i];
        g_bsum[db * NN_BLOCKS_X + blockIdx.x] = w;
        __threadfence();
        unsigned t = atomicAdd(&g_count, 1u);
        s_last = (t == NN_BLOCKS - 1);
    }
    __syncthreads();

    if (s_last) {
        __threadfence();
        float w = g_bsum[tid] + g_bsum[tid + NN_THREADS];   // 512 partials
#pragma unroll
        for (int o = 16; o; o >>= 1) w += __shfl_down_sync(FULLMASK, w, o);
        if (lane == 0) sred[wid] = w;
        __syncthreads();
        if (tid == 0) {
            float tot = 0.f;
#pragma unroll
            for (int i = 0; i < 8; i++) tot += sred[i];
            out[0] = tot;
            g_count = 0u;               // reset for next graph replay
        }
    }
}

extern "C" void kernel_launch(void* const* d_in, const int* in_sizes, int n_in,
                              void* d_out, int out_size) {
    const float* p1 = (const float*)d_in[0];
    const float* p2 = (const float*)d_in[1];
    float* out = (float*)d_out;

    sort_kernel<<<8, SORT_THREADS>>>(p1, p2);
    nn_kernel<<<dim3(NN_BLOCKS_X, 8), NN_THREADS>>>(out);
}